// round 7
// baseline (speedup 1.0000x reference)
#include <cuda_runtime.h>
#include <math.h>

#define Tt 128
#define Bb 32
#define Ii 256
#define Hh 1024
#define Oo 128
#define TBm (Tt*Bb)      /* 4096 */
#define BHm (Bb*Hh)      /* 32768 */
#define NBLK 128
#define HSTR 36          /* hS row stride: multiple of 4 -> float4-aligned */

// ---------------- scratch (device globals; no allocations allowed) ----------------
static __device__ float g_Hstate[(Tt+1)*BHm];      // [t][b][h], t=0..T
static __device__ float g_hT[2*Hh*Bb];             // ping-pong transposed state [h][b]
static __device__ float g_Xin[(size_t)TBm*Hh];     // x @ W_in^T, [t*B+b][h]
static __device__ float g_Cb[(size_t)TBm*Hh];      // c then A (in-place)
static __device__ float g_Err[TBm*Oo];
static __device__ float g_Part[4*(size_t)Hh*Hh];   // split-K partials
static __device__ unsigned g_flagv[NBLK];          // per-block barrier flags

// ---------------- double-buffered fp32 tiled GEMM ----------------
// MODE 0 = NN: C[m,n] = sum_k A[m,k]*B[k,n]
// MODE 1 = NT: C[m,n] = sum_k A[m,k]*B[n,k]
// MODE 2 = TN: C[m,n] = sum_k A[k,m]*B[k,n]
// EPI  0 = plain; 2 = val *= (1 - aux^2)  (tanh' fusion)
// gridDim.z > 1: raw partials to Cpart[z][M*N] (alpha/EPI applied in reduce_k).
template<int MODE, int BM, int BN, int BK, int TMv, int TNv, int EPI>
__global__ __launch_bounds__(256) void gemm_k(
    const float* __restrict__ A, const float* __restrict__ B,
    float* __restrict__ C, float* __restrict__ Cpart,
    const float* __restrict__ aux,
    int Md, int Nd, int Kd, float alpha, int kslice)
{
    constexpr int NA = BM * BK / 1024;      // float4 loads per thread for A tile
    constexpr int NB = BN * BK / 1024;
    __shared__ float As[2][BK][BM];
    __shared__ float Bs[2][BK][BN];
    const int t  = threadIdx.x;
    const int tx = t & 15, ty = t >> 4;
    const int m0 = blockIdx.y * BM, n0 = blockIdx.x * BN;
    const int kbeg = blockIdx.z * kslice;
    const int kend = kbeg + kslice;

    float4 pa[NA], pb[NB];

    auto ldg_tile = [&](int kk) {
        #pragma unroll
        for (int i = 0; i < NA; i++) {
            int lin = t + i * 256;
            if (MODE == 0 || MODE == 1) {            // A[m,k]
                int kv = BK / 4, m = lin / kv, kq = (lin % kv) * 4;
                pa[i] = *(const float4*)&A[(size_t)(m0 + m) * Kd + kk + kq];
            } else {                                 // A[k,m]
                int mv = BM / 4, k = lin / mv, mq = (lin % mv) * 4;
                pa[i] = *(const float4*)&A[(size_t)(kk + k) * Md + m0 + mq];
            }
        }
        #pragma unroll
        for (int i = 0; i < NB; i++) {
            int lin = t + i * 256;
            if (MODE == 0 || MODE == 2) {            // B[k,n]
                int nv = BN / 4, k = lin / nv, nq = (lin % nv) * 4;
                pb[i] = *(const float4*)&B[(size_t)(kk + k) * Nd + n0 + nq];
            } else {                                 // B[n,k]
                int kv = BK / 4, n = lin / kv, kq = (lin % kv) * 4;
                pb[i] = *(const float4*)&B[(size_t)(n0 + n) * Kd + kk + kq];
            }
        }
    };
    auto sts_tile = [&](int buf) {
        #pragma unroll
        for (int i = 0; i < NA; i++) {
            int lin = t + i * 256;
            if (MODE == 0 || MODE == 1) {
                int kv = BK / 4, m = lin / kv, kq = (lin % kv) * 4;
                As[buf][kq + 0][m] = pa[i].x; As[buf][kq + 1][m] = pa[i].y;
                As[buf][kq + 2][m] = pa[i].z; As[buf][kq + 3][m] = pa[i].w;
            } else {
                int mv = BM / 4, k = lin / mv, mq = (lin % mv) * 4;
                *(float4*)&As[buf][k][mq] = pa[i];
            }
        }
        #pragma unroll
        for (int i = 0; i < NB; i++) {
            int lin = t + i * 256;
            if (MODE == 0 || MODE == 2) {
                int nv = BN / 4, k = lin / nv, nq = (lin % nv) * 4;
                *(float4*)&Bs[buf][k][nq] = pb[i];
            } else {
                int kv = BK / 4, n = lin / kv, kq = (lin % kv) * 4;
                Bs[buf][kq + 0][n] = pb[i].x; Bs[buf][kq + 1][n] = pb[i].y;
                Bs[buf][kq + 2][n] = pb[i].z; Bs[buf][kq + 3][n] = pb[i].w;
            }
        }
    };

    float acc[TMv][TNv];
    #pragma unroll
    for (int i = 0; i < TMv; i++)
        #pragma unroll
        for (int j = 0; j < TNv; j++) acc[i][j] = 0.f;

    ldg_tile(kbeg);
    sts_tile(0);
    __syncthreads();

    int buf = 0;
    for (int kk = kbeg; kk < kend; kk += BK) {
        const bool more = (kk + BK < kend);
        if (more) ldg_tile(kk + BK);

        #pragma unroll
        for (int k = 0; k < BK; k++) {
            float a[TMv], bb[TNv];
            #pragma unroll
            for (int i = 0; i < TMv; i += 4) {
                float4 v = *(const float4*)&As[buf][k][ty * TMv + i];
                a[i] = v.x; a[i + 1] = v.y; a[i + 2] = v.z; a[i + 3] = v.w;
            }
            #pragma unroll
            for (int j = 0; j < TNv; j += 4) {
                float4 v = *(const float4*)&Bs[buf][k][tx * TNv + j];
                bb[j] = v.x; bb[j + 1] = v.y; bb[j + 2] = v.z; bb[j + 3] = v.w;
            }
            #pragma unroll
            for (int i = 0; i < TMv; i++)
                #pragma unroll
                for (int j = 0; j < TNv; j++)
                    acc[i][j] = fmaf(a[i], bb[j], acc[i][j]);
        }

        if (more) sts_tile(buf ^ 1);
        __syncthreads();
        buf ^= 1;
    }

    float scale = alpha;
    float* dst = C;
    if (gridDim.z > 1) { dst = Cpart + (size_t)blockIdx.z * Md * Nd; scale = 1.f; }
    #pragma unroll
    for (int i = 0; i < TMv; i++) {
        size_t row = (size_t)(m0 + ty * TMv + i) * Nd + n0 + tx * TNv;
        #pragma unroll
        for (int j = 0; j < TNv; j += 4) {
            float4 v;
            v.x = scale * acc[i][j];     v.y = scale * acc[i][j + 1];
            v.z = scale * acc[i][j + 2]; v.w = scale * acc[i][j + 3];
            if (EPI == 2) {
                float4 hn = *(const float4*)&aux[row + j];
                v.x *= (1.f - hn.x * hn.x); v.y *= (1.f - hn.y * hn.y);
                v.z *= (1.f - hn.z * hn.z); v.w *= (1.f - hn.w * hn.w);
            }
            *(float4*)&dst[row + j] = v;
        }
    }
}

// ---------------- flag-array grid barrier ----------------
// Arrive: each block release-stores its own flag word (parallel, no atomic
// serialization). Complete: warp 0 polls all NBLK flags (4 acquire-loads/lane).
// gen is absolute & monotonic across graph replays (base read from own flag).
__device__ __forceinline__ void grid_barrier(unsigned gen)
{
    __syncthreads();
    if (threadIdx.x == 0) {
        __threadfence();
        asm volatile("st.release.gpu.global.u32 [%0], %1;"
                     :: "l"(&g_flagv[blockIdx.x]), "r"(gen) : "memory");
    }
    if (threadIdx.x < 32) {
        const unsigned* f = &g_flagv[threadIdx.x * 4];
        bool ok;
        do {
            unsigned f0, f1, f2, f3;
            asm volatile("ld.acquire.gpu.global.u32 %0, [%1];" : "=r"(f0) : "l"(f + 0) : "memory");
            asm volatile("ld.acquire.gpu.global.u32 %0, [%1];" : "=r"(f1) : "l"(f + 1) : "memory");
            asm volatile("ld.acquire.gpu.global.u32 %0, [%1];" : "=r"(f2) : "l"(f + 2) : "memory");
            asm volatile("ld.acquire.gpu.global.u32 %0, [%1];" : "=r"(f3) : "l"(f + 3) : "memory");
            ok = ((int)(f0 - gen) >= 0) && ((int)(f1 - gen) >= 0) &&
                 ((int)(f2 - gen) >= 0) && ((int)(f3 - gen) >= 0);
        } while (__ballot_sync(0xffffffffu, ok) != 0xffffffffu);
    }
    __syncthreads();
}

// ---------------- persistent forward scan ----------------
// 128 blocks x 256 threads, 1 block/SM (~190KB smem -> full wave co-resident).
// Block owns 8 h rows; W_hh slice cached in smem for ALL steps.
// Each warp stages + consumes its own 128-k slice of h (warp-private, no sync).
// Epilogue: pre-tanh sums staged through red2[b][hr] so Hst/xin/hf accesses
// are 32B-contiguous per thread-octet.
__global__ void __launch_bounds__(256) rnn_scan_k(
    const float* __restrict__ h0, const float* __restrict__ Whh,
    const float* __restrict__ Xin, float* __restrict__ hT,
    float* __restrict__ Hst, float* __restrict__ hf)
{
    extern __shared__ float sm[];
    float* Ws   = sm;                        // [8][1024]
    float* hS   = sm + 8 * 1024;             // [1024][HSTR]
    float* red  = hS + 1024 * HSTR;          // [8][8][33]
    float* red2 = red + 64 * 33;             // [32][9]

    const int t = threadIdx.x;
    const int lane = t & 31, w = t >> 5;
    const int hbase = blockIdx.x * 8;

    unsigned gen = g_flagv[blockIdx.x];      // barrier generation base

    // cache Whh slice (8 rows x 1024) in smem
    for (int i = t; i < 2048; i += 256) {
        int r = i >> 8;
        int c = (i & 255) << 2;
        *(float4*)&Ws[r * 1024 + c] = *(const float4*)&Whh[(size_t)(hbase + r) * Hh + c];
    }
    // seed h0 (coalesced mapping: b = t>>3, hr = t&7)
    {
        int b = t >> 3, hr = t & 7;
        float v = h0[b * Hh + hbase + hr];
        hT[(hbase + hr) * Bb + b] = v;
        Hst[b * Hh + hbase + hr] = v;
    }
    gen += 1;
    grid_barrier(gen);

    const int k0 = w << 7;                  // warp's k range [k0, k0+128)
    for (int tt = 0; tt < Tt; tt++) {
        const float* hin  = hT + (size_t)(tt & 1) * Hh * Bb;
        float*       hout = hT + (size_t)((tt + 1) & 1) * Hh * Bb;
        const float* xin  = Xin + (size_t)tt * BHm;

        // warp-private stage of its own k slice: hin[k*32+b] -> hS[k*HSTR+b]
        #pragma unroll 4
        for (int i = lane; i < 1024; i += 32) {
            int k = k0 + (i >> 3);
            int bq = (i & 7) << 2;
            *(float4*)&hS[k * HSTR + bq] = *(const float4*)&hin[k * Bb + bq];
        }

        // warp w: k in [k0, k0+128), all 8 h rows, lane = batch
        float acc[8];
        #pragma unroll
        for (int i = 0; i < 8; i++) acc[i] = 0.f;
        #pragma unroll 4
        for (int k = k0; k < k0 + 128; k += 4) {
            float hv0 = hS[(k + 0) * HSTR + lane];
            float hv1 = hS[(k + 1) * HSTR + lane];
            float hv2 = hS[(k + 2) * HSTR + lane];
            float hv3 = hS[(k + 3) * HSTR + lane];
            #pragma unroll
            for (int hr = 0; hr < 8; hr++) {
                float4 wv = *(const float4*)&Ws[hr * 1024 + k];   // broadcast
                acc[hr] = fmaf(hv0, wv.x, acc[hr]);
                acc[hr] = fmaf(hv1, wv.y, acc[hr]);
                acc[hr] = fmaf(hv2, wv.z, acc[hr]);
                acc[hr] = fmaf(hv3, wv.w, acc[hr]);
            }
        }
        #pragma unroll
        for (int hr = 0; hr < 8; hr++)
            red[(w * 8 + hr) * 33 + lane] = acc[hr];
        __syncthreads();

        // phase 1: cross-warp reduce -> red2[b][hr]   (hr = t>>5, b = lane)
        {
            int hr = t >> 5, b = lane;
            float s = 0.f;
            #pragma unroll
            for (int wi = 0; wi < 8; wi++)
                s += red[(wi * 8 + hr) * 33 + b];
            red2[b * 9 + hr] = s;
        }
        __syncthreads();

        // phase 2: tanh + writes, coalesced mapping (b = t>>3, hr = t&7)
        {
            int b = t >> 3, hr = t & 7;
            float s = red2[b * 9 + hr];
            float v = tanhf(s + xin[b * Hh + hbase + hr]);
            hout[(hbase + hr) * Bb + b] = v;
            Hst[(size_t)(tt + 1) * BHm + b * Hh + hbase + hr] = v;
            if (tt == Tt - 1) hf[b * Hh + hbase + hr] = v;
        }
        gen += 1;
        grid_barrier(gen);
    }
}

// ---------------- small kernels ----------------
// A[s] = c[s] + D[s+1]*A[s+1],  D[s+1] = diag(W_hh) * (1 - Hstate[s+1]^2)
__global__ void back_scan_k(float* __restrict__ Cb, const float* __restrict__ Hst,
                            const float* __restrict__ Whh)
{
    int idx = blockIdx.x * blockDim.x + threadIdx.x;   // b*H + h
    int h = idx & 1023;
    float dw = Whh[(size_t)h * Hh + h];
    float a = Cb[(size_t)(Tt - 1) * BHm + idx];
    for (int s = Tt - 2; s >= 0; s--) {
        float hn = Hst[(size_t)(s + 1) * BHm + idx];
        float d = dw * (1.f - hn * hn);
        a = Cb[(size_t)s * BHm + idx] + d * a;
        Cb[(size_t)s * BHm + idx] = a;
    }
}

// EPI 0: out = alpha * sum(part).   EPI 1: out = sum(part); eout = out - aux.
template<int EPI>
__global__ void reduce_k(const float* __restrict__ part, float* __restrict__ out,
                         const float* __restrict__ aux, float* __restrict__ eout,
                         int MN, int S, float alpha)
{
    int i = blockIdx.x * blockDim.x + threadIdx.x;
    if (i < MN) {
        float s = 0.f;
        for (int z = 0; z < S; z++) s += part[(size_t)z * MN + i];
        s *= alpha;
        out[i] = s;
        if (EPI == 1) eout[i] = s - aux[i];
    }
}

// ---------------- orchestration ----------------
extern "C" void kernel_launch(void* const* d_in, const int* in_sizes, int n_in,
                              void* d_out, int out_size)
{
    const float* x    = (const float*)d_in[0];   // [T,B,I]
    const float* tgt  = (const float*)d_in[1];   // [T,B,O]
    const float* h0   = (const float*)d_in[2];   // [B,H]
    const float* Win  = (const float*)d_in[3];   // [H,I]
    const float* Whh  = (const float*)d_in[4];   // [H,H]
    const float* Wout = (const float*)d_in[5];   // [O,H]

    float* out   = (float*)d_out;
    float* ys    = out;                      // [T*B, O]
    float* hf    = ys + (size_t)TBm * Oo;    // [B, H]
    float* gwout = hf + BHm;                 // [O, H]
    float* gwih  = gwout + (size_t)Oo * Hh;  // [H, I]
    float* gwhh  = gwih + (size_t)Hh * Ii;   // [H, H]

    float *Hst, *hT, *Xin, *Cb, *Err, *Part;
    cudaGetSymbolAddress((void**)&Hst,  g_Hstate);
    cudaGetSymbolAddress((void**)&hT,   g_hT);
    cudaGetSymbolAddress((void**)&Xin,  g_Xin);
    cudaGetSymbolAddress((void**)&Cb,   g_Cb);
    cudaGetSymbolAddress((void**)&Err,  g_Err);
    cudaGetSymbolAddress((void**)&Part, g_Part);

    // persistent scan needs >48KB dynamic smem
    const int scan_smem = (8 * 1024 + 1024 * HSTR + 64 * 33 + 32 * 9)
                          * (int)sizeof(float);
    cudaFuncSetAttribute(rnn_scan_k, cudaFuncAttributeMaxDynamicSharedMemorySize,
                         scan_smem);

    // Xin = x @ Win^T   (NT: M=4096, N=1024, K=256)
    gemm_k<1,128,128,16,8,8,0><<<dim3(Hh/128, TBm/128, 1), 256>>>(
        x, Win, Xin, nullptr, nullptr, TBm, Hh, Ii, 1.f, Ii);

    // persistent forward scan (fuses h0 transpose + all 128 steps + hf)
    rnn_scan_k<<<NBLK, 256, scan_smem>>>(h0, Whh, Xin, hT, Hst, hf);

    // ys = Hnew @ Wout^T  (NT: M=4096, N=128, K=1024, 128x64 tiles, split-K 2)
    gemm_k<1,128,64,16,8,4,0><<<dim3(Oo/64, TBm/128, 2), 256>>>(
        Hst + BHm, Wout, nullptr, Part, nullptr, TBm, Oo, Hh, 0.f, Hh/2);
    // reduce + fused Err = ys - tgt
    reduce_k<1><<<(TBm*Oo + 255)/256, 256>>>(Part, ys, tgt, Err, TBm*Oo, 2, 1.f);

    // c = (Err @ Wout) * (1 - Hnew^2)   [rank-128 collapse, fused tanh']
    gemm_k<0,128,128,16,8,8,2><<<dim3(Hh/128, TBm/128, 1), 256>>>(
        Err, Wout, Cb, nullptr, Hst + BHm, TBm, Hh, Oo, 1.f, Oo);

    // backward scan: A[s] = c[s] + D[s+1]*A[s+1] (in-place in Cb)
    back_scan_k<<<BHm/256, 256>>>(Cb, Hst, Whh);

    // g_wih = (1e-3/B) * A^T @ x   (TN: M=1024, N=256, K=4096, 128x128, split 8)
    gemm_k<2,128,128,16,8,8,0><<<dim3(Ii/128, Hh/128, 8), 256>>>(
        Cb, x, nullptr, Part, nullptr, Hh, Ii, TBm, 0.f, TBm/8);
    reduce_k<0><<<(Hh*Ii + 255)/256, 256>>>(Part, gwih, nullptr, nullptr,
                                            Hh*Ii, 8, 1e-3f/Bb);

    // g_whh = (1e-5/B) * A^T @ Hprev  (TN: M=N=1024, K=4096, 128x128, split 4)
    gemm_k<2,128,128,16,8,8,0><<<dim3(Hh/128, Hh/128, 4), 256>>>(
        Cb, Hst, nullptr, Part, nullptr, Hh, Hh, TBm, 0.f, TBm/4);
    reduce_k<0><<<(Hh*Hh + 255)/256, 256>>>(Part, gwhh, nullptr, nullptr,
                                            Hh*Hh, 4, 1e-5f/Bb);

    // g_wout = (1/B) * Err^T @ Hnew  (TN: M=128, N=1024, K=4096, 128x128, split 16)
    gemm_k<2,128,128,16,8,8,0><<<dim3(Hh/128, Oo/128, 16), 256>>>(
        Err, Hst + BHm, nullptr, Part, nullptr, Oo, Hh, TBm, 0.f, TBm/16);
    reduce_k<0><<<(Oo*Hh + 255)/256, 256>>>(Part, gwout, nullptr, nullptr,
                                            Oo*Hh, 16, 1.f/Bb);
}